// round 13
// baseline (speedup 1.0000x reference)
#include <cuda_runtime.h>

#define B_ 2
#define T_ 128
#define N_ 64
#define D_ 128
#define H_ 8
#define DK_ 16
#define DE_ 32
#define LW_ 8
#define BN_ 128
#define TT_ 16

#define CP 12     // per-(tl,s) cell pitch: 8 h + 4 pad (48B => 16B-aligned cells)
#define KVP 132   // K/V row pitch
#define QXP 132   // q/xo tile pitch
#define PRP 133   // prob row pitch (distinct banks for tlq row groups)

// smem float offsets
#define SC_OFF  0         // 16*128*12 = 24576
#define KV_OFF  24576     // 128*132 = 16896
#define QX_OFF  41472     // 16*132 = 2112
#define WGP_OFF 43584     // 128 ull = 256 floats
#define WU_OFF  43840     // 256
#define BG2_OFF 44096     // 8
#define BUS_OFF 44104     // 32
#define BOS_OFF 44136     // 128
#define MK_OFF  44264     // 128 ints
#define MKB_OFF 44392     // 4 uints
#define SM_TOT  44396     // floats -> 177,584 bytes

typedef unsigned long long ull;

__device__ __forceinline__ void ffma2(ull &d, ull a, ull b) {
    asm("fma.rn.f32x2 %0, %1, %2, %0;" : "+l"(d) : "l"(a), "l"(b));
}
__device__ __forceinline__ ull fadd2(ull a, ull b) {
    ull r; asm("add.rn.f32x2 %0, %1, %2;" : "=l"(r) : "l"(a), "l"(b)); return r;
}
__device__ __forceinline__ ull fmul2(ull a, ull b) {
    ull r; asm("mul.rn.f32x2 %0, %1, %2;" : "=l"(r) : "l"(a), "l"(b)); return r;
}
__device__ __forceinline__ ull pack2(float x, float y) {
    ull r; asm("mov.b64 %0, {%1, %2};" : "=l"(r) : "f"(x), "f"(y)); return r;
}
__device__ __forceinline__ float2 unpack2(ull v) {
    float2 r; asm("mov.b64 {%0, %1}, %2;" : "=f"(r.x), "=f"(r.y) : "l"(v)); return r;
}
__device__ __forceinline__ ull shflx2(ull v, int m) {
    float2 f = unpack2(v);
    f.x = __shfl_xor_sync(0xffffffffu, f.x, m);
    f.y = __shfl_xor_sync(0xffffffffu, f.y, m);
    return pack2(f.x, f.y);
}
__device__ __forceinline__ float clip5(float v) {
    return fminf(fmaxf(v, -5.0f), 5.0f);
}

__device__ float g_Q[BN_ * T_ * D_];
__device__ float g_K[BN_ * T_ * D_];
__device__ float g_V[BN_ * T_ * D_];

// ============================================================================
// Kernel A: qkv projection (exact 254us-run config: NO d-loop unroll pragma).
// ============================================================================
__global__ __launch_bounds__(256) void qkv_kernel(
    const float* __restrict__ node, const float* __restrict__ Wqkv,
    const float* __restrict__ bqkv) {
    extern __shared__ float xs[];   // [128][66]
    const int half = blockIdx.x;
    const int bn = blockIdx.y;
    const int b = bn >> 6, n = bn & 63;
    const int t0 = half * 64;
    const int tid = threadIdx.x;

    for (int i = tid; i < 64 * 128; i += 256) {
        int t = i >> 7, d = i & 127;
        xs[d * 66 + t] = node[((b * T_ + t0 + t) * N_ + n) * D_ + d];
    }
    __syncthreads();

    for (int g = tid; g < 768; g += 256) {
        int q4 = g % 96;
        int tg = g / 96;
        ull acc[4][4];
        #pragma unroll
        for (int k = 0; k < 4; k++) {
            float bv = bqkv[q4 * 4 + k];
            ull bp = pack2(bv, bv);
            #pragma unroll
            for (int tp = 0; tp < 4; tp++) acc[tp][k] = bp;
        }
        for (int d = 0; d < 128; d++) {
            float4 wf = *(const float4*)(Wqkv + d * 384 + q4 * 4);
            ull w0 = pack2(wf.x, wf.x), w1 = pack2(wf.y, wf.y);
            ull w2 = pack2(wf.z, wf.z), w3 = pack2(wf.w, wf.w);
            #pragma unroll
            for (int tp = 0; tp < 4; tp++) {
                ull xt = *(const ull*)(xs + d * 66 + tg * 8 + tp * 2);
                ffma2(acc[tp][0], xt, w0);
                ffma2(acc[tp][1], xt, w1);
                ffma2(acc[tp][2], xt, w2);
                ffma2(acc[tp][3], xt, w3);
            }
        }
        #pragma unroll
        for (int k = 0; k < 4; k++) {
            int d3 = q4 * 4 + k;
            int c = d3 % 3, hd = d3 / 3;
            float* dst = (c == 0) ? g_Q : (c == 1) ? g_K : g_V;
            int rb = bn * T_ + t0 + tg * 8;
            #pragma unroll
            for (int tp = 0; tp < 4; tp++) {
                float2 f = unpack2(acc[tp][k]);
                dst[(rb + tp * 2    ) * D_ + hd] = f.x;
                dst[(rb + tp * 2 + 1) * D_ + hd] = f.y;
            }
        }
    }
}

// ============================================================================
// Kernel B: fused attention (254us base; ONLY phase-1 lane map changed).
// ============================================================================
__global__ __launch_bounds__(1024) void attn_kernel(
    const float* __restrict__ tv, const int* __restrict__ mask,
    const float* __restrict__ lmask,
    const float* __restrict__ Wg, const float* __restrict__ bg,
    const float* __restrict__ Wout, const float* __restrict__ bout,
    const float* __restrict__ Wupd, const float* __restrict__ bupd,
    float* __restrict__ out) {
    extern __shared__ float sm[];
    float* sc  = sm + SC_OFF;   // [tl][s][CP] cells; later prob rows [h*16+tl][PRP]
    float* kv  = sm + KV_OFF;   // [s][KVP], swizzled h-cells
    float* qx  = sm + QX_OFF;   // [16][QXP]
    ull*   wgp = (ull*)(sm + WGP_OFF);
    float* wu  = sm + WU_OFF;
    ull*   bg2 = (ull*)(sm + BG2_OFF);
    float* bus = sm + BUS_OFF;
    float* bos = sm + BOS_OFF;
    int*   mk  = (int*)(sm + MK_OFF);
    unsigned* mkb = (unsigned*)(sm + MKB_OFF);

    const int tile = blockIdx.x;
    const int bn = blockIdx.y;
    const int b = bn >> 6, n = bn & 63;
    const int t0 = tile * TT_;
    const int tid = threadIdx.x;
    const int lane = tid & 31, warp = tid >> 5;

    // ---- phase 0: loads ----
    if (tid < 128) {
        bos[tid] = bout[tid];
        mk[tid] = mask[b * T_ + tid];
        int j = tid >> 5, e = tid & 31;
        wgp[j * 32 + e] = pack2(Wg[e * H_ + 2 * j], Wg[e * H_ + 2 * j + 1]);
    }
    if (tid >= 128 && tid < 384) wu[tid - 128] = Wupd[tid - 128];
    if (tid >= 384 && tid < 388) {   // mask bitmask words
        int w = tid - 384;
        unsigned bits = 0;
        for (int i = 0; i < 32; i++)
            bits |= (mask[b * T_ + w * 32 + i] != 0 ? 1u : 0u) << i;
        mkb[w] = bits;
    }
    if (tid < 32) bus[tid] = bupd[tid];
    if (tid < 4)  bg2[tid] = pack2(bg[2 * tid], bg[2 * tid + 1]);
    if (tid < 512) {  // Q tile
        int tl = tid >> 5, c4 = tid & 31;
        float4 v = *(const float4*)(g_Q + (bn * T_ + t0 + tl) * D_ + c4 * 4);
        *(float4*)(qx + tl * QXP + c4 * 4) = v;
    }
    #pragma unroll
    for (int ii = 0; ii < 4; ii++) {  // K: swizzled h-cells
        int i = tid + ii * 1024;
        int s = i >> 5, c4 = i & 31, h = c4 >> 2, m = c4 & 3;
        float4 v = *(const float4*)(g_K + (bn * T_ + s) * D_ + c4 * 4);
        *(float4*)(kv + s * KVP + ((h + (s >> 3)) & 7) * 16 + m * 4) = v;
    }
    __syncthreads();

    // ---- phase 1: scores = (q.k)/4 ----
    // NEW lane map: h = lane&7 (minor), sq = lane>>3; warp = (tl-pair, s-quarter).
    // 8 h-lanes tile each 512B kv row completely (swizzle is an h-permutation)
    // => 4 wf per K LDS.128; cell stores span 4 cells (176B) => 2 wf.
    {
        const int h1 = lane & 7;
        const int sq = lane >> 3;            // 0..3
        const int tlA = (warp >> 2) * 2;     // tl pair base
        const int sqb = (warp & 3) * 32;     // s quarter base
        ull qa[8], qb[8];
        {
            const ulonglong2* qap = (const ulonglong2*)(qx + tlA * QXP + h1 * DK_);
            const ulonglong2* qbp = (const ulonglong2*)(qx + (tlA + 1) * QXP + h1 * DK_);
            ulonglong2 a0 = qap[0], a1 = qap[1], a2 = qap[2], a3 = qap[3];
            qa[0] = a0.x; qa[1] = a0.y; qa[2] = a1.x; qa[3] = a1.y;
            qa[4] = a2.x; qa[5] = a2.y; qa[6] = a3.x; qa[7] = a3.y;
            ulonglong2 b0 = qbp[0], b1 = qbp[1], b2 = qbp[2], b3 = qbp[3];
            qb[0] = b0.x; qb[1] = b0.y; qb[2] = b1.x; qb[3] = b1.y;
            qb[4] = b2.x; qb[5] = b2.y; qb[6] = b3.x; qb[7] = b3.y;
        }
        #pragma unroll
        for (int i = 0; i < 8; i++) {
            int s = sqb + i * 4 + sq;
            const ulonglong2* kc = (const ulonglong2*)(
                kv + s * KVP + ((h1 + (s >> 3)) & 7) * 16);
            ulonglong2 k0 = kc[0], k1 = kc[1], k2 = kc[2], k3 = kc[3];
            ull aA = 0ull, aB = 0ull;
            ffma2(aA, qa[0], k0.x); ffma2(aA, qa[1], k0.y);
            ffma2(aA, qa[2], k1.x); ffma2(aA, qa[3], k1.y);
            ffma2(aA, qa[4], k2.x); ffma2(aA, qa[5], k2.y);
            ffma2(aA, qa[6], k3.x); ffma2(aA, qa[7], k3.y);
            ffma2(aB, qb[0], k0.x); ffma2(aB, qb[1], k0.y);
            ffma2(aB, qb[2], k1.x); ffma2(aB, qb[3], k1.y);
            ffma2(aB, qb[4], k2.x); ffma2(aB, qb[5], k2.y);
            ffma2(aB, qb[6], k3.x); ffma2(aB, qb[7], k3.y);
            float2 fA = unpack2(aA), fB = unpack2(aB);
            sc[(tlA * 128 + s) * CP + h1]       = (fA.x + fA.y) * 0.25f;
            sc[((tlA + 1) * 128 + s) * CP + h1] = (fB.x + fB.y) * 0.25f;
        }
    }

    // ---- tv band preload + V prefetch (regs), hidden behind barrier ----
    const int it2 = lane >> 3, eg = lane & 7;
    float4 tvf[3]; int cellp[3]; bool val[3];
    #pragma unroll
    for (int r = 0; r < 3; r++) {
        val[r] = false; cellp[r] = 0;
        tvf[r] = make_float4(0.f, 0.f, 0.f, 0.f);
        int g = warp + r * 32;
        if (g < 68) {
            int p = g * 4 + it2;
            if (p < 272) {
                int tl = p / 17, jj = p % 17;
                int t = t0 + tl, s = t - LW_ + jj;
                if (s >= 0 && s < T_ && mk[s] != 0) {
                    val[r] = true;
                    cellp[r] = (tl * 128 + s) * CP;
                    tvf[r] = *(const float4*)(
                        tv + ((size_t)(bn * T_ + t) * T_ + s) * DE_ + eg * 4);
                }
            }
        }
    }
    float4 vreg[4];
    #pragma unroll
    for (int ii = 0; ii < 4; ii++) {
        int i = tid + ii * 1024;
        int s = i >> 5, c4 = i & 31;
        vreg[ii] = *(const float4*)(g_V + (bn * T_ + s) * D_ + c4 * 4);
    }
    __syncthreads();

    // ---- phase 2: band bias += tv @ W_g + b_g  (packed h-pairs) ----
    #pragma unroll
    for (int r = 0; r < 3; r++) {
        ull v0 = 0ull, v1 = 0ull, v2 = 0ull, v3 = 0ull;
        if (val[r]) {
            float c0 = tvf[r].x, c1 = tvf[r].y, c2 = tvf[r].z, c3 = tvf[r].w;
            #pragma unroll
            for (int c = 0; c < 4; c++) {
                float cv = (c == 0) ? c0 : (c == 1) ? c1 : (c == 2) ? c2 : c3;
                ull tc = pack2(cv, cv);
                ffma2(v0, tc, wgp[0 * 32 + eg * 4 + c]);
                ffma2(v1, tc, wgp[1 * 32 + eg * 4 + c]);
                ffma2(v2, tc, wgp[2 * 32 + eg * 4 + c]);
                ffma2(v3, tc, wgp[3 * 32 + eg * 4 + c]);
            }
        }
        #pragma unroll
        for (int o = 1; o <= 4; o <<= 1) {
            v0 = fadd2(v0, shflx2(v0, o));
            v1 = fadd2(v1, shflx2(v1, o));
            v2 = fadd2(v2, shflx2(v2, o));
            v3 = fadd2(v3, shflx2(v3, o));
        }
        if (eg == 0 && val[r]) {
            ulonglong2* cv2 = (ulonglong2*)(sc + cellp[r]);
            ulonglong2 o0 = cv2[0], o1 = cv2[1];
            o0.x = fadd2(o0.x, fadd2(v0, bg2[0]));
            o0.y = fadd2(o0.y, fadd2(v1, bg2[1]));
            o1.x = fadd2(o1.x, fadd2(v2, bg2[2]));
            o1.y = fadd2(o1.y, fadd2(v3, bg2[3]));
            cv2[0] = o0; cv2[1] = o1;
        }
    }
    // V into kv (K fully consumed)
    #pragma unroll
    for (int ii = 0; ii < 4; ii++) {
        int i = tid + ii * 1024;
        int s = i >> 5, c4 = i & 31, h = c4 >> 2, m = c4 & 3;
        *(float4*)(kv + s * KVP + ((h + (s >> 3)) & 7) * 16 + m * 4) = vreg[ii];
    }
    __syncthreads();

    // ---- phase 5: tv_out = clip/mask(scores) @ W_upd + b_upd ----
    // (exact 254us version: broadcast vector cell loads, hoisted mask per j)
    {
        const size_t OFF = (size_t)B_ * T_ * N_ * D_;
        float wuf[8], sw = 0.f;
        #pragma unroll
        for (int h = 0; h < 8; h++) { wuf[h] = wu[h * 32 + lane]; sw += wuf[h]; }
        float bu = bus[lane];
        const float defacc = fmaf(1e-28f, sw, bu);
        float* outb = out + OFF + ((size_t)(bn * T_ + t0) * T_) * DE_ + lane;
        #pragma unroll
        for (int j = 0; j < 4; j++) {
            const int s = warp + j * 32;
            float* op = outb + (size_t)s * DE_;
            if (mk[s] == 0) {
                #pragma unroll
                for (int tl = 0; tl < 16; tl++)
                    op[tl * 128 * DE_] = defacc;
            } else {
                const float* cp0 = sc + s * CP;
                #pragma unroll 4
                for (int tl = 0; tl < 16; tl++) {
                    const ulonglong2* cu2 =
                        (const ulonglong2*)(cp0 + tl * 128 * CP);
                    ulonglong2 ca = cu2[0], cb = cu2[1];
                    float2 c0 = unpack2(ca.x), c1 = unpack2(ca.y);
                    float2 c2 = unpack2(cb.x), c3 = unpack2(cb.y);
                    float acc = bu;
                    acc = fmaf(clip5(c0.x), wuf[0], acc);
                    acc = fmaf(clip5(c0.y), wuf[1], acc);
                    acc = fmaf(clip5(c1.x), wuf[2], acc);
                    acc = fmaf(clip5(c1.y), wuf[3], acc);
                    acc = fmaf(clip5(c2.x), wuf[4], acc);
                    acc = fmaf(clip5(c2.y), wuf[5], acc);
                    acc = fmaf(clip5(c3.x), wuf[6], acc);
                    acc = fmaf(clip5(c3.y), wuf[7], acc);
                    op[tl * 128 * DE_] = acc;
                }
            }
        }
    }
    __syncthreads();

    // ---- phase 6: softmax. warp = (tl, s-half), lane = s. exp in regs; ----
    // conflict-free 16B cell loads; MUFU skipped for masked s; probs written
    // ROW-MAJOR [h*16+tl][PRP] into the (now dead) cell region: coalesced STS.
    {
        const int tl6 = warp >> 1;
        const int half6 = warp & 1;
        ull ex[2][4];
        ull sac0 = 0ull, sac1 = 0ull, sac2 = 0ull, sac3 = 0ull;
        unsigned kb[2];
        #pragma unroll
        for (int r = 0; r < 2; r++) {
            int s = half6 * 64 + r * 32 + lane;
            unsigned kbit = (mkb[half6 * 2 + r] >> lane) & 1u;
            kb[r] = kbit;
            const ulonglong2* cu2 = (const ulonglong2*)(sc + (tl6 * 128 + s) * CP);
            ulonglong2 ca = cu2[0], cb = cu2[1];
            float2 c0 = unpack2(ca.x), c1 = unpack2(ca.y);
            float2 c2 = unpack2(cb.x), c3 = unpack2(cb.y);
            float e0 = 1.f, e1 = 1.f, e2 = 1.f, e3 = 1.f;
            float e4 = 1.f, e5 = 1.f, e6 = 1.f, e7 = 1.f;
            if (kbit) {          // masked s: score=1e-28 -> exp=1 (no MUFU)
                e0 = __expf(clip5(c0.x)); e1 = __expf(clip5(c0.y));
                e2 = __expf(clip5(c1.x)); e3 = __expf(clip5(c1.y));
                e4 = __expf(clip5(c2.x)); e5 = __expf(clip5(c2.y));
                e6 = __expf(clip5(c3.x)); e7 = __expf(clip5(c3.y));
            }
            ex[r][0] = pack2(e0, e1); ex[r][1] = pack2(e2, e3);
            ex[r][2] = pack2(e4, e5); ex[r][3] = pack2(e6, e7);
            sac0 = fadd2(sac0, ex[r][0]); sac1 = fadd2(sac1, ex[r][1]);
            sac2 = fadd2(sac2, ex[r][2]); sac3 = fadd2(sac3, ex[r][3]);
        }
        #pragma unroll
        for (int o = 16; o > 0; o >>= 1) {
            sac0 = fadd2(sac0, shflx2(sac0, o));
            sac1 = fadd2(sac1, shflx2(sac1, o));
            sac2 = fadd2(sac2, shflx2(sac2, o));
            sac3 = fadd2(sac3, shflx2(sac3, o));
        }
        ull* partq = (ull*)qx;   // [tl][half][4 ull]; Q dead after phase 1
        if (lane < 4) {
            ull v = (lane == 0) ? sac0 : (lane == 1) ? sac1
                  : (lane == 2) ? sac2 : sac3;
            partq[(tl6 * 2 + half6) * 4 + lane] = v;
        }
        __syncthreads();   // also: all cell READS complete beyond this point
        ull t0u = fadd2(partq[tl6 * 8 + 0], partq[tl6 * 8 + 4]);
        ull t1u = fadd2(partq[tl6 * 8 + 1], partq[tl6 * 8 + 5]);
        ull t2u = fadd2(partq[tl6 * 8 + 2], partq[tl6 * 8 + 6]);
        ull t3u = fadd2(partq[tl6 * 8 + 3], partq[tl6 * 8 + 7]);
        float2 f0 = unpack2(t0u), f1 = unpack2(t1u);
        float2 f2 = unpack2(t2u), f3 = unpack2(t3u);
        float mytot = (lane == 0) ? f0.x : (lane == 1) ? f0.y
                    : (lane == 2) ? f1.x : (lane == 3) ? f1.y
                    : (lane == 4) ? f2.x : (lane == 5) ? f2.y
                    : (lane == 6) ? f3.x : f3.y;
        float myinv = 1.0f;
        if (lane < 8) myinv = 1.0f / mytot;
        float iv[8];
        #pragma unroll
        for (int h = 0; h < 8; h++)
            iv[h] = __shfl_sync(0xffffffffu, myinv, h);
        ull ip0 = pack2(iv[0], iv[1]), ip1 = pack2(iv[2], iv[3]);
        ull ip2 = pack2(iv[4], iv[5]), ip3 = pack2(iv[6], iv[7]);
        #pragma unroll
        for (int r = 0; r < 2; r++) {
            int s = half6 * 64 + r * 32 + lane;
            ull p0 = 0ull, p1 = 0ull, p2 = 0ull, p3 = 0ull;
            if (kb[r]) {
                p0 = fmul2(ex[r][0], ip0); p1 = fmul2(ex[r][1], ip1);
                p2 = fmul2(ex[r][2], ip2); p3 = fmul2(ex[r][3], ip3);
            }
            float2 q0 = unpack2(p0), q1 = unpack2(p1);
            float2 q2 = unpack2(p2), q3 = unpack2(p3);
            float* pr = sc + tl6 * PRP + s;   // row (h*16+tl6), coalesced in s
            pr[(0 * 16) * PRP] = q0.x; pr[(1 * 16) * PRP] = q0.y;
            pr[(2 * 16) * PRP] = q1.x; pr[(3 * 16) * PRP] = q1.y;
            pr[(4 * 16) * PRP] = q2.x; pr[(5 * 16) * PRP] = q2.y;
            pr[(6 * 16) * PRP] = q3.x; pr[(7 * 16) * PRP] = q3.y;
        }
    }
    __syncthreads();

    // ---- phase 7: xo = attn @ V; probs from row-major layout ----
    {
        const int dq = tid & 7;
        const int tlq = (tid >> 3) & 3;
        const int h7 = (tid >> 5) & 7;
        const int chunk = tid >> 8;
        const unsigned mbits = mkb[chunk];
        ull acc0 = 0ull, acc1 = 0ull, acc2 = 0ull, acc3 = 0ull;
        const float* pb0 = sc + (h7 * 16 + tlq * 4 + 0) * PRP + chunk * 32;
        const float* pb1 = sc + (h7 * 16 + tlq * 4 + 1) * PRP + chunk * 32;
        const float* pb2 = sc + (h7 * 16 + tlq * 4 + 2) * PRP + chunk * 32;
        const float* pb3 = sc + (h7 * 16 + tlq * 4 + 3) * PRP + chunk * 32;
        #pragma unroll
        for (int g = 0; g < 4; g++) {
            const int sb = chunk * 32 + g * 8;
            const float* kvg = kv + sb * KVP
                + ((h7 + chunk * 4 + g) & 7) * 16 + dq * 2;
            const float* pg0 = pb0 + g * 8;
            const float* pg1 = pb1 + g * 8;
            const float* pg2 = pb2 + g * 8;
            const float* pg3 = pb3 + g * 8;
            const unsigned mb = (mbits >> (g * 8)) & 0xffu;
            #pragma unroll
            for (int si = 0; si < 8; si++) {
                if ((mb >> si) & 1) {
                    ull v = *(const ull*)(kvg + si * KVP);
                    float a0 = pg0[si], a1 = pg1[si];
                    float a2 = pg2[si], a3 = pg3[si];
                    ffma2(acc0, pack2(a0, a0), v);
                    ffma2(acc1, pack2(a1, a1), v);
                    ffma2(acc2, pack2(a2, a2), v);
                    ffma2(acc3, pack2(a3, a3), v);
                }
            }
        }
        __syncthreads();   // all prob + V reads done; kv reusable for partials
        ull* part = (ull*)(sm + KV_OFF);   // [chunk][h][tl16][dq]
        part[((chunk * 8 + h7) * 16 + tlq * 4 + 0) * 8 + dq] = acc0;
        part[((chunk * 8 + h7) * 16 + tlq * 4 + 1) * 8 + dq] = acc1;
        part[((chunk * 8 + h7) * 16 + tlq * 4 + 2) * 8 + dq] = acc2;
        part[((chunk * 8 + h7) * 16 + tlq * 4 + 3) * 8 + dq] = acc3;
        __syncthreads();
        const int ho = tid >> 7, tlo = (tid >> 3) & 15, dqo = tid & 7;
        ull ssum = part[((0 * 8 + ho) * 16 + tlo) * 8 + dqo];
        ssum = fadd2(ssum, part[((1 * 8 + ho) * 16 + tlo) * 8 + dqo]);
        ssum = fadd2(ssum, part[((2 * 8 + ho) * 16 + tlo) * 8 + dqo]);
        ssum = fadd2(ssum, part[((3 * 8 + ho) * 16 + tlo) * 8 + dqo]);
        *(ull*)(qx + tlo * QXP + ho * DK_ + dqo * 2) = ssum;
    }
    __syncthreads();

    // ---- phase 8: out = xo @ W_out + b_out; thread = (tl-pair, dp, d-half) ----
    {
        const int ds = tid & 1, dp = (tid >> 1) & 63, tlh = tid >> 7;
        const int tlA = tlh * 2;
        ull acc0 = 0ull, acc1 = 0ull;
        const float* x0p = qx + tlA * QXP;
        const float* x1p = x0p + QXP;
        #pragma unroll 4
        for (int dd = 0; dd < 64; dd++) {
            int d = ds * 64 + dd;
            ull w = *(const ull*)(Wout + d * D_ + dp * 2);
            ffma2(acc0, pack2(x0p[d], x0p[d]), w);
            ffma2(acc1, pack2(x1p[d], x1p[d]), w);
        }
        acc0 = fadd2(acc0, shflx2(acc0, 1));
        acc1 = fadd2(acc1, shflx2(acc1, 1));
        if (ds == 0) {
            ull bb = pack2(bos[dp * 2], bos[dp * 2 + 1]);
            acc0 = fadd2(acc0, bb);
            acc1 = fadd2(acc1, bb);
            int t = t0 + tlA;
            float2 f0 = unpack2(acc0), f1 = unpack2(acc1);
            *(float2*)(out + ((size_t)(b * T_ + t) * N_ + n) * D_ + dp * 2) = f0;
            *(float2*)(out + ((size_t)(b * T_ + t + 1) * N_ + n) * D_ + dp * 2) = f1;
        }
    }
}

// ============================================================================
extern "C" void kernel_launch(void* const* d_in, const int* in_sizes, int n_in,
                              void* d_out, int out_size) {
    const float* node  = (const float*)d_in[0];
    const float* tv    = (const float*)d_in[1];
    const int*   mask  = (const int*)d_in[2];
    const float* lmask = (const float*)d_in[3];
    const float* Wqkv  = (const float*)d_in[4];
    const float* bqkv  = (const float*)d_in[5];
    const float* Wg    = (const float*)d_in[6];
    const float* bg    = (const float*)d_in[7];
    const float* Wout  = (const float*)d_in[8];
    const float* bout  = (const float*)d_in[9];
    const float* Wupd  = (const float*)d_in[10];
    const float* bupd  = (const float*)d_in[11];
    float* out = (float*)d_out;

    const int smemA = 128 * 66 * 4;   // 33,792 B
    const int smemB = SM_TOT * 4;     // 177,584 B
    cudaFuncSetAttribute(qkv_kernel,  cudaFuncAttributeMaxDynamicSharedMemorySize, smemA);
    cudaFuncSetAttribute(attn_kernel, cudaFuncAttributeMaxDynamicSharedMemorySize, smemB);

    qkv_kernel<<<dim3(2, BN_), 256, smemA>>>(node, Wqkv, bqkv);
    attn_kernel<<<dim3(T_ / TT_, BN_), 1024, smemB>>>(
        tv, mask, lmask, Wg, bg, Wout, bout, Wupd, bupd, out);
}

// round 14
// speedup vs baseline: 1.2410x; 1.2410x over previous
#include <cuda_runtime.h>

#define B_ 2
#define T_ 128
#define N_ 64
#define D_ 128
#define H_ 8
#define DK_ 16
#define DE_ 32
#define LW_ 8
#define BN_ 128
#define TT_ 16

#define CP 12     // per-(tl,s) cell pitch: 8 h + 4 pad (48B => 16B-aligned cells)
#define KVP 132   // K/V row pitch
#define QXP 132   // q/xo tile pitch
#define PRP 133   // prob row pitch (distinct banks for tlq row groups)

// smem float offsets
#define SC_OFF  0         // 16*128*12 = 24576
#define KV_OFF  24576     // 128*132 = 16896
#define QX_OFF  41472     // 16*132 = 2112
#define WGP_OFF 43584     // 128 ull = 256 floats
#define WU_OFF  43840     // 256
#define BG2_OFF 44096     // 8
#define BUS_OFF 44104     // 32
#define BOS_OFF 44136     // 128
#define MK_OFF  44264     // 128 ints
#define MKB_OFF 44392     // 4 uints
#define SM_TOT  44396     // floats -> 177,584 bytes

typedef unsigned long long ull;

__device__ __forceinline__ void ffma2(ull &d, ull a, ull b) {
    asm("fma.rn.f32x2 %0, %1, %2, %0;" : "+l"(d) : "l"(a), "l"(b));
}
__device__ __forceinline__ ull fadd2(ull a, ull b) {
    ull r; asm("add.rn.f32x2 %0, %1, %2;" : "=l"(r) : "l"(a), "l"(b)); return r;
}
__device__ __forceinline__ ull fmul2(ull a, ull b) {
    ull r; asm("mul.rn.f32x2 %0, %1, %2;" : "=l"(r) : "l"(a), "l"(b)); return r;
}
__device__ __forceinline__ ull pack2(float x, float y) {
    ull r; asm("mov.b64 %0, {%1, %2};" : "=l"(r) : "f"(x), "f"(y)); return r;
}
__device__ __forceinline__ float2 unpack2(ull v) {
    float2 r; asm("mov.b64 {%0, %1}, %2;" : "=f"(r.x), "=f"(r.y) : "l"(v)); return r;
}
__device__ __forceinline__ ull shflx2(ull v, int m) {
    float2 f = unpack2(v);
    f.x = __shfl_xor_sync(0xffffffffu, f.x, m);
    f.y = __shfl_xor_sync(0xffffffffu, f.y, m);
    return pack2(f.x, f.y);
}
__device__ __forceinline__ float clip5(float v) {
    return fminf(fmaxf(v, -5.0f), 5.0f);
}

__device__ float g_Q[BN_ * T_ * D_];
__device__ float g_K[BN_ * T_ * D_];
__device__ float g_V[BN_ * T_ * D_];

// ============================================================================
// Kernel A: qkv projection (exact 254us-run config).
// ============================================================================
__global__ __launch_bounds__(256) void qkv_kernel(
    const float* __restrict__ node, const float* __restrict__ Wqkv,
    const float* __restrict__ bqkv) {
    extern __shared__ float xs[];   // [128][66]
    const int half = blockIdx.x;
    const int bn = blockIdx.y;
    const int b = bn >> 6, n = bn & 63;
    const int t0 = half * 64;
    const int tid = threadIdx.x;

    for (int i = tid; i < 64 * 128; i += 256) {
        int t = i >> 7, d = i & 127;
        xs[d * 66 + t] = node[((b * T_ + t0 + t) * N_ + n) * D_ + d];
    }
    __syncthreads();

    for (int g = tid; g < 768; g += 256) {
        int q4 = g % 96;
        int tg = g / 96;
        ull acc[4][4];
        #pragma unroll
        for (int k = 0; k < 4; k++) {
            float bv = bqkv[q4 * 4 + k];
            ull bp = pack2(bv, bv);
            #pragma unroll
            for (int tp = 0; tp < 4; tp++) acc[tp][k] = bp;
        }
        for (int d = 0; d < 128; d++) {
            float4 wf = *(const float4*)(Wqkv + d * 384 + q4 * 4);
            ull w0 = pack2(wf.x, wf.x), w1 = pack2(wf.y, wf.y);
            ull w2 = pack2(wf.z, wf.z), w3 = pack2(wf.w, wf.w);
            #pragma unroll
            for (int tp = 0; tp < 4; tp++) {
                ull xt = *(const ull*)(xs + d * 66 + tg * 8 + tp * 2);
                ffma2(acc[tp][0], xt, w0);
                ffma2(acc[tp][1], xt, w1);
                ffma2(acc[tp][2], xt, w2);
                ffma2(acc[tp][3], xt, w3);
            }
        }
        #pragma unroll
        for (int k = 0; k < 4; k++) {
            int d3 = q4 * 4 + k;
            int c = d3 % 3, hd = d3 / 3;
            float* dst = (c == 0) ? g_Q : (c == 1) ? g_K : g_V;
            int rb = bn * T_ + t0 + tg * 8;
            #pragma unroll
            for (int tp = 0; tp < 4; tp++) {
                float2 f = unpack2(acc[tp][k]);
                dst[(rb + tp * 2    ) * D_ + hd] = f.x;
                dst[(rb + tp * 2 + 1) * D_ + hd] = f.y;
            }
        }
    }
}

// ============================================================================
// Kernel B: fused attention (254us base + flat pre-clip pass).
// ============================================================================
__global__ __launch_bounds__(1024) void attn_kernel(
    const float* __restrict__ tv, const int* __restrict__ mask,
    const float* __restrict__ lmask,
    const float* __restrict__ Wg, const float* __restrict__ bg,
    const float* __restrict__ Wout, const float* __restrict__ bout,
    const float* __restrict__ Wupd, const float* __restrict__ bupd,
    float* __restrict__ out) {
    extern __shared__ float sm[];
    float* sc  = sm + SC_OFF;   // [tl][s][CP] cells; later prob rows [h*16+tl][PRP]
    float* kv  = sm + KV_OFF;   // [s][KVP], swizzled h-cells
    float* qx  = sm + QX_OFF;   // [16][QXP]
    ull*   wgp = (ull*)(sm + WGP_OFF);
    float* wu  = sm + WU_OFF;
    ull*   bg2 = (ull*)(sm + BG2_OFF);
    float* bus = sm + BUS_OFF;
    float* bos = sm + BOS_OFF;
    int*   mk  = (int*)(sm + MK_OFF);
    unsigned* mkb = (unsigned*)(sm + MKB_OFF);

    const int tile = blockIdx.x;
    const int bn = blockIdx.y;
    const int b = bn >> 6, n = bn & 63;
    const int t0 = tile * TT_;
    const int tid = threadIdx.x;
    const int lane = tid & 31, warp = tid >> 5;

    // ---- phase 0: loads ----
    if (tid < 128) {
        bos[tid] = bout[tid];
        mk[tid] = mask[b * T_ + tid];
        int j = tid >> 5, e = tid & 31;
        wgp[j * 32 + e] = pack2(Wg[e * H_ + 2 * j], Wg[e * H_ + 2 * j + 1]);
    }
    if (tid >= 128 && tid < 384) wu[tid - 128] = Wupd[tid - 128];
    if (tid >= 384 && tid < 388) {   // mask bitmask words
        int w = tid - 384;
        unsigned bits = 0;
        for (int i = 0; i < 32; i++)
            bits |= (mask[b * T_ + w * 32 + i] != 0 ? 1u : 0u) << i;
        mkb[w] = bits;
    }
    if (tid < 32) bus[tid] = bupd[tid];
    if (tid < 4)  bg2[tid] = pack2(bg[2 * tid], bg[2 * tid + 1]);
    if (tid < 512) {  // Q tile
        int tl = tid >> 5, c4 = tid & 31;
        float4 v = *(const float4*)(g_Q + (bn * T_ + t0 + tl) * D_ + c4 * 4);
        *(float4*)(qx + tl * QXP + c4 * 4) = v;
    }
    #pragma unroll
    for (int ii = 0; ii < 4; ii++) {  // K: swizzled h-cells
        int i = tid + ii * 1024;
        int s = i >> 5, c4 = i & 31, h = c4 >> 2, m = c4 & 3;
        float4 v = *(const float4*)(g_K + (bn * T_ + s) * D_ + c4 * 4);
        *(float4*)(kv + s * KVP + ((h + (s >> 3)) & 7) * 16 + m * 4) = v;
    }
    __syncthreads();

    // ---- phase 1: scores = (q.k)/4 ; thread = (h, tl-pair, s-group16) ----
    {
        const int h1 = tid >> 7, tlp = (tid >> 4) & 7, sg = tid & 15;
        const int tlA = tlp * 2;
        const ulonglong2* qap = (const ulonglong2*)(qx + tlA * QXP + h1 * DK_);
        const ulonglong2* qbp = (const ulonglong2*)(qx + (tlA + 1) * QXP + h1 * DK_);
        ulonglong2 qa0 = qap[0], qa1 = qap[1], qa2 = qap[2], qa3 = qap[3];
        ulonglong2 qb0 = qbp[0], qb1 = qbp[1], qb2 = qbp[2], qb3 = qbp[3];
        #pragma unroll
        for (int i = 0; i < 8; i++) {
            int s = sg + 16 * i;
            const ulonglong2* kc = (const ulonglong2*)(
                kv + s * KVP + ((h1 + (s >> 3)) & 7) * 16);
            ulonglong2 k0 = kc[0], k1 = kc[1], k2 = kc[2], k3 = kc[3];
            ull aA = 0ull, aB = 0ull;
            ffma2(aA, qa0.x, k0.x); ffma2(aA, qa0.y, k0.y);
            ffma2(aA, qa1.x, k1.x); ffma2(aA, qa1.y, k1.y);
            ffma2(aA, qa2.x, k2.x); ffma2(aA, qa2.y, k2.y);
            ffma2(aA, qa3.x, k3.x); ffma2(aA, qa3.y, k3.y);
            ffma2(aB, qb0.x, k0.x); ffma2(aB, qb0.y, k0.y);
            ffma2(aB, qb1.x, k1.x); ffma2(aB, qb1.y, k1.y);
            ffma2(aB, qb2.x, k2.x); ffma2(aB, qb2.y, k2.y);
            ffma2(aB, qb3.x, k3.x); ffma2(aB, qb3.y, k3.y);
            float2 fA = unpack2(aA), fB = unpack2(aB);
            sc[(tlA * 128 + s) * CP + h1]       = (fA.x + fA.y) * 0.25f;
            sc[((tlA + 1) * 128 + s) * CP + h1] = (fB.x + fB.y) * 0.25f;
        }
    }

    // ---- tv band preload + V prefetch (regs), hidden behind barrier ----
    const int it2 = lane >> 3, eg = lane & 7;
    float4 tvf[3]; int cellp[3]; bool val[3];
    #pragma unroll
    for (int r = 0; r < 3; r++) {
        val[r] = false; cellp[r] = 0;
        tvf[r] = make_float4(0.f, 0.f, 0.f, 0.f);
        int g = warp + r * 32;
        if (g < 68) {
            int p = g * 4 + it2;
            if (p < 272) {
                int tl = p / 17, jj = p % 17;
                int t = t0 + tl, s = t - LW_ + jj;
                if (s >= 0 && s < T_ && mk[s] != 0) {
                    val[r] = true;
                    cellp[r] = (tl * 128 + s) * CP;
                    tvf[r] = *(const float4*)(
                        tv + ((size_t)(bn * T_ + t) * T_ + s) * DE_ + eg * 4);
                }
            }
        }
    }
    float4 vreg[4];
    #pragma unroll
    for (int ii = 0; ii < 4; ii++) {
        int i = tid + ii * 1024;
        int s = i >> 5, c4 = i & 31;
        vreg[ii] = *(const float4*)(g_V + (bn * T_ + s) * D_ + c4 * 4);
    }
    __syncthreads();

    // ---- phase 2: band bias += tv @ W_g + b_g  (packed h-pairs) ----
    #pragma unroll
    for (int r = 0; r < 3; r++) {
        ull v0 = 0ull, v1 = 0ull, v2 = 0ull, v3 = 0ull;
        if (val[r]) {
            float c0 = tvf[r].x, c1 = tvf[r].y, c2 = tvf[r].z, c3 = tvf[r].w;
            #pragma unroll
            for (int c = 0; c < 4; c++) {
                float cv = (c == 0) ? c0 : (c == 1) ? c1 : (c == 2) ? c2 : c3;
                ull tc = pack2(cv, cv);
                ffma2(v0, tc, wgp[0 * 32 + eg * 4 + c]);
                ffma2(v1, tc, wgp[1 * 32 + eg * 4 + c]);
                ffma2(v2, tc, wgp[2 * 32 + eg * 4 + c]);
                ffma2(v3, tc, wgp[3 * 32 + eg * 4 + c]);
            }
        }
        #pragma unroll
        for (int o = 1; o <= 4; o <<= 1) {
            v0 = fadd2(v0, shflx2(v0, o));
            v1 = fadd2(v1, shflx2(v1, o));
            v2 = fadd2(v2, shflx2(v2, o));
            v3 = fadd2(v3, shflx2(v3, o));
        }
        if (eg == 0 && val[r]) {
            ulonglong2* cv2 = (ulonglong2*)(sc + cellp[r]);
            ulonglong2 o0 = cv2[0], o1 = cv2[1];
            o0.x = fadd2(o0.x, fadd2(v0, bg2[0]));
            o0.y = fadd2(o0.y, fadd2(v1, bg2[1]));
            o1.x = fadd2(o1.x, fadd2(v2, bg2[2]));
            o1.y = fadd2(o1.y, fadd2(v3, bg2[3]));
            cv2[0] = o0; cv2[1] = o1;
        }
    }
    // V into kv (K fully consumed)
    #pragma unroll
    for (int ii = 0; ii < 4; ii++) {
        int i = tid + ii * 1024;
        int s = i >> 5, c4 = i & 31, h = c4 >> 2, m = c4 & 3;
        *(float4*)(kv + s * KVP + ((h + (s >> 3)) & 7) * 16 + m * 4) = vreg[ii];
    }
    __syncthreads();

    // ---- pre-clip pass: clip every score ONCE (flat, coalesced, incl. pad) ----
    // Replaces the 32x-redundant per-lane clips in phases 5/6.
    {
        float4* base = (float4*)sc;
        #pragma unroll
        for (int k = 0; k < 6; k++) {
            float4* p = base + tid + k * 1024;   // 6144 float4 = whole region
            float4 v = *p;
            v.x = clip5(v.x); v.y = clip5(v.y);
            v.z = clip5(v.z); v.w = clip5(v.w);
            *p = v;
        }
    }
    __syncthreads();

    // ---- phase 5: tv_out = scores(pre-clipped) @ W_upd + b_upd ----
    {
        const size_t OFF = (size_t)B_ * T_ * N_ * D_;
        float wuf[8], sw = 0.f;
        #pragma unroll
        for (int h = 0; h < 8; h++) { wuf[h] = wu[h * 32 + lane]; sw += wuf[h]; }
        float bu = bus[lane];
        const float defacc = fmaf(1e-28f, sw, bu);
        float* outb = out + OFF + ((size_t)(bn * T_ + t0) * T_) * DE_ + lane;
        #pragma unroll
        for (int j = 0; j < 4; j++) {
            const int s = warp + j * 32;
            float* op = outb + (size_t)s * DE_;
            if (mk[s] == 0) {
                #pragma unroll
                for (int tl = 0; tl < 16; tl++)
                    op[tl * 128 * DE_] = defacc;
            } else {
                const float* cp0 = sc + s * CP;
                #pragma unroll 4
                for (int tl = 0; tl < 16; tl++) {
                    const ulonglong2* cu2 =
                        (const ulonglong2*)(cp0 + tl * 128 * CP);
                    ulonglong2 ca = cu2[0], cb = cu2[1];
                    float2 c0 = unpack2(ca.x), c1 = unpack2(ca.y);
                    float2 c2 = unpack2(cb.x), c3 = unpack2(cb.y);
                    float acc = bu;
                    acc = fmaf(c0.x, wuf[0], acc);
                    acc = fmaf(c0.y, wuf[1], acc);
                    acc = fmaf(c1.x, wuf[2], acc);
                    acc = fmaf(c1.y, wuf[3], acc);
                    acc = fmaf(c2.x, wuf[4], acc);
                    acc = fmaf(c2.y, wuf[5], acc);
                    acc = fmaf(c3.x, wuf[6], acc);
                    acc = fmaf(c3.y, wuf[7], acc);
                    op[tl * 128 * DE_] = acc;
                }
            }
        }
    }
    __syncthreads();

    // ---- phase 6: softmax (cells pre-clipped). warp = (tl, s-half). ----
    {
        const int tl6 = warp >> 1;
        const int half6 = warp & 1;
        ull ex[2][4];
        ull sac0 = 0ull, sac1 = 0ull, sac2 = 0ull, sac3 = 0ull;
        unsigned kb[2];
        #pragma unroll
        for (int r = 0; r < 2; r++) {
            int s = half6 * 64 + r * 32 + lane;
            unsigned kbit = (mkb[half6 * 2 + r] >> lane) & 1u;
            kb[r] = kbit;
            const ulonglong2* cu2 = (const ulonglong2*)(sc + (tl6 * 128 + s) * CP);
            ulonglong2 ca = cu2[0], cb = cu2[1];
            float2 c0 = unpack2(ca.x), c1 = unpack2(ca.y);
            float2 c2 = unpack2(cb.x), c3 = unpack2(cb.y);
            float e0 = 1.f, e1 = 1.f, e2 = 1.f, e3 = 1.f;
            float e4 = 1.f, e5 = 1.f, e6 = 1.f, e7 = 1.f;
            if (kbit) {          // masked s: score=1e-28 -> exp=1 (no MUFU)
                e0 = __expf(c0.x); e1 = __expf(c0.y);
                e2 = __expf(c1.x); e3 = __expf(c1.y);
                e4 = __expf(c2.x); e5 = __expf(c2.y);
                e6 = __expf(c3.x); e7 = __expf(c3.y);
            }
            ex[r][0] = pack2(e0, e1); ex[r][1] = pack2(e2, e3);
            ex[r][2] = pack2(e4, e5); ex[r][3] = pack2(e6, e7);
            sac0 = fadd2(sac0, ex[r][0]); sac1 = fadd2(sac1, ex[r][1]);
            sac2 = fadd2(sac2, ex[r][2]); sac3 = fadd2(sac3, ex[r][3]);
        }
        #pragma unroll
        for (int o = 16; o > 0; o >>= 1) {
            sac0 = fadd2(sac0, shflx2(sac0, o));
            sac1 = fadd2(sac1, shflx2(sac1, o));
            sac2 = fadd2(sac2, shflx2(sac2, o));
            sac3 = fadd2(sac3, shflx2(sac3, o));
        }
        ull* partq = (ull*)qx;   // [tl][half][4 ull]; Q dead after phase 1
        if (lane < 4) {
            ull v = (lane == 0) ? sac0 : (lane == 1) ? sac1
                  : (lane == 2) ? sac2 : sac3;
            partq[(tl6 * 2 + half6) * 4 + lane] = v;
        }
        __syncthreads();   // also: all cell READS complete beyond this point
        ull t0u = fadd2(partq[tl6 * 8 + 0], partq[tl6 * 8 + 4]);
        ull t1u = fadd2(partq[tl6 * 8 + 1], partq[tl6 * 8 + 5]);
        ull t2u = fadd2(partq[tl6 * 8 + 2], partq[tl6 * 8 + 6]);
        ull t3u = fadd2(partq[tl6 * 8 + 3], partq[tl6 * 8 + 7]);
        float2 f0 = unpack2(t0u), f1 = unpack2(t1u);
        float2 f2 = unpack2(t2u), f3 = unpack2(t3u);
        float mytot = (lane == 0) ? f0.x : (lane == 1) ? f0.y
                    : (lane == 2) ? f1.x : (lane == 3) ? f1.y
                    : (lane == 4) ? f2.x : (lane == 5) ? f2.y
                    : (lane == 6) ? f3.x : f3.y;
        float myinv = 1.0f;
        if (lane < 8) myinv = 1.0f / mytot;
        float iv[8];
        #pragma unroll
        for (int h = 0; h < 8; h++)
            iv[h] = __shfl_sync(0xffffffffu, myinv, h);
        ull ip0 = pack2(iv[0], iv[1]), ip1 = pack2(iv[2], iv[3]);
        ull ip2 = pack2(iv[4], iv[5]), ip3 = pack2(iv[6], iv[7]);
        #pragma unroll
        for (int r = 0; r < 2; r++) {
            int s = half6 * 64 + r * 32 + lane;
            ull p0 = 0ull, p1 = 0ull, p2 = 0ull, p3 = 0ull;
            if (kb[r]) {
                p0 = fmul2(ex[r][0], ip0); p1 = fmul2(ex[r][1], ip1);
                p2 = fmul2(ex[r][2], ip2); p3 = fmul2(ex[r][3], ip3);
            }
            float2 q0 = unpack2(p0), q1 = unpack2(p1);
            float2 q2 = unpack2(p2), q3 = unpack2(p3);
            float* pr = sc + tl6 * PRP + s;   // row (h*16+tl6), coalesced in s
            pr[(0 * 16) * PRP] = q0.x; pr[(1 * 16) * PRP] = q0.y;
            pr[(2 * 16) * PRP] = q1.x; pr[(3 * 16) * PRP] = q1.y;
            pr[(4 * 16) * PRP] = q2.x; pr[(5 * 16) * PRP] = q2.y;
            pr[(6 * 16) * PRP] = q3.x; pr[(7 * 16) * PRP] = q3.y;
        }
    }
    __syncthreads();

    // ---- phase 7: xo = attn @ V; probs from row-major layout ----
    {
        const int dq = tid & 7;
        const int tlq = (tid >> 3) & 3;
        const int h7 = (tid >> 5) & 7;
        const int chunk = tid >> 8;
        const unsigned mbits = mkb[chunk];
        ull acc0 = 0ull, acc1 = 0ull, acc2 = 0ull, acc3 = 0ull;
        const float* pb0 = sc + (h7 * 16 + tlq * 4 + 0) * PRP + chunk * 32;
        const float* pb1 = sc + (h7 * 16 + tlq * 4 + 1) * PRP + chunk * 32;
        const float* pb2 = sc + (h7 * 16 + tlq * 4 + 2) * PRP + chunk * 32;
        const float* pb3 = sc + (h7 * 16 + tlq * 4 + 3) * PRP + chunk * 32;
        #pragma unroll
        for (int g = 0; g < 4; g++) {
            const int sb = chunk * 32 + g * 8;
            const float* kvg = kv + sb * KVP
                + ((h7 + chunk * 4 + g) & 7) * 16 + dq * 2;
            const float* pg0 = pb0 + g * 8;
            const float* pg1 = pb1 + g * 8;
            const float* pg2 = pb2 + g * 8;
            const float* pg3 = pb3 + g * 8;
            const unsigned mb = (mbits >> (g * 8)) & 0xffu;
            #pragma unroll
            for (int si = 0; si < 8; si++) {
                if ((mb >> si) & 1) {
                    ull v = *(const ull*)(kvg + si * KVP);
                    float a0 = pg0[si], a1 = pg1[si];
                    float a2 = pg2[si], a3 = pg3[si];
                    ffma2(acc0, pack2(a0, a0), v);
                    ffma2(acc1, pack2(a1, a1), v);
                    ffma2(acc2, pack2(a2, a2), v);
                    ffma2(acc3, pack2(a3, a3), v);
                }
            }
        }
        __syncthreads();   // all prob + V reads done; kv reusable for partials
        ull* part = (ull*)(sm + KV_OFF);   // [chunk][h][tl16][dq]
        part[((chunk * 8 + h7) * 16 + tlq * 4 + 0) * 8 + dq] = acc0;
        part[((chunk * 8 + h7) * 16 + tlq * 4 + 1) * 8 + dq] = acc1;
        part[((chunk * 8 + h7) * 16 + tlq * 4 + 2) * 8 + dq] = acc2;
        part[((chunk * 8 + h7) * 16 + tlq * 4 + 3) * 8 + dq] = acc3;
        __syncthreads();
        const int ho = tid >> 7, tlo = (tid >> 3) & 15, dqo = tid & 7;
        ull ssum = part[((0 * 8 + ho) * 16 + tlo) * 8 + dqo];
        ssum = fadd2(ssum, part[((1 * 8 + ho) * 16 + tlo) * 8 + dqo]);
        ssum = fadd2(ssum, part[((2 * 8 + ho) * 16 + tlo) * 8 + dqo]);
        ssum = fadd2(ssum, part[((3 * 8 + ho) * 16 + tlo) * 8 + dqo]);
        *(ull*)(qx + tlo * QXP + ho * DK_ + dqo * 2) = ssum;
    }
    __syncthreads();

    // ---- phase 8: out = xo @ W_out + b_out; thread = (tl-pair, dp, d-half) ----
    {
        const int ds = tid & 1, dp = (tid >> 1) & 63, tlh = tid >> 7;
        const int tlA = tlh * 2;
        ull acc0 = 0ull, acc1 = 0ull;
        const float* x0p = qx + tlA * QXP;
        const float* x1p = x0p + QXP;
        #pragma unroll 4
        for (int dd = 0; dd < 64; dd++) {
            int d = ds * 64 + dd;
            ull w = *(const ull*)(Wout + d * D_ + dp * 2);
            ffma2(acc0, pack2(x0p[d], x0p[d]), w);
            ffma2(acc1, pack2(x1p[d], x1p[d]), w);
        }
        acc0 = fadd2(acc0, shflx2(acc0, 1));
        acc1 = fadd2(acc1, shflx2(acc1, 1));
        if (ds == 0) {
            ull bb = pack2(bos[dp * 2], bos[dp * 2 + 1]);
            acc0 = fadd2(acc0, bb);
            acc1 = fadd2(acc1, bb);
            int t = t0 + tlA;
            float2 f0 = unpack2(acc0), f1 = unpack2(acc1);
            *(float2*)(out + ((size_t)(b * T_ + t) * N_ + n) * D_ + dp * 2) = f0;
            *(float2*)(out + ((size_t)(b * T_ + t + 1) * N_ + n) * D_ + dp * 2) = f1;
        }
    }
}

// ============================================================================
extern "C" void kernel_launch(void* const* d_in, const int* in_sizes, int n_in,
                              void* d_out, int out_size) {
    const float* node  = (const float*)d_in[0];
    const float* tv    = (const float*)d_in[1];
    const int*   mask  = (const int*)d_in[2];
    const float* lmask = (const float*)d_in[3];
    const float* Wqkv  = (const float*)d_in[4];
    const float* bqkv  = (const float*)d_in[5];
    const float* Wg    = (const float*)d_in[6];
    const float* bg    = (const float*)d_in[7];
    const float* Wout  = (const float*)d_in[8];
    const float* bout  = (const float*)d_in[9];
    const float* Wupd  = (const float*)d_in[10];
    const float* bupd  = (const float*)d_in[11];
    float* out = (float*)d_out;

    const int smemA = 128 * 66 * 4;   // 33,792 B
    const int smemB = SM_TOT * 4;     // 177,584 B
    cudaFuncSetAttribute(qkv_kernel,  cudaFuncAttributeMaxDynamicSharedMemorySize, smemA);
    cudaFuncSetAttribute(attn_kernel, cudaFuncAttributeMaxDynamicSharedMemorySize, smemB);

    qkv_kernel<<<dim3(2, BN_), 256, smemA>>>(node, Wqkv, bqkv);
    attn_kernel<<<dim3(T_ / TT_, BN_), 1024, smemB>>>(
        tv, mask, lmask, Wg, bg, Wout, bout, Wupd, bupd, out);
}